// round 14
// baseline (speedup 1.0000x reference)
#include <cuda_runtime.h>
#include <cuda_bf16.h>
#include <math.h>
#include <stdint.h>

// ---------------------------------------------------------------------------
// Problem constants
// ---------------------------------------------------------------------------
#define NTOK 8192           // 8 * 32 * 32 tokens at stride 32
#define C    768            // channels
#define K2C  384            // C/2 (k-pair rows of packed weights)
#define NE   4              // experts

#define S4_ELEMS  50331648  // 8*96*256*256
#define S8_ELEMS  25165824  // 8*192*128*128
#define S16_ELEMS 12582912  // 8*384*64*64
#define OFF_S8   50331648
#define OFF_S16  75497472
#define OFF_S32  88080384

// GEMM tiling (bf16 m16n8k16, block 128x128, 8 warps of 64x32, 256 threads)
#define TBM 128
#define TBN 128
#define TBK 32              // k per smem stage (2 x k16 mma steps)
#define AS_W 20             // u32 words per A smem row (32 bf16 data + pad)
#define BS_W 136            // u32 words per B smem row (128 data + 8 pad)
#define A_STAGE_W (TBM * AS_W)        // 2560 words
#define B_STAGE_W ((TBK/2) * BS_W)    // 2176 words
#define SMEM_GEMM_BYTES ((2*A_STAGE_W + 2*B_STAGE_W) * 4)           // 37888 (<48KB)

#define MT (NTOK / TBM)     // 64 m-tiles
#define NT (C / TBN)        // 6  n-tiles
#define NB_COPY 148         // copy blocks PREPENDED per GEMM launch (proven R6/R8)
#define NB_CONV 256         // expert-weight convert blocks (gate launch only)

// ---------------------------------------------------------------------------
// Scratch (device globals: no allocation allowed)
// ---------------------------------------------------------------------------
__device__ __nv_bfloat16 g_Xb[NTOK * C];   // tokens hi bf16
__device__ __nv_bfloat16 g_Xl[NTOK * C];   // tokens lo bf16 (residual; for fixup)
__device__ __nv_bfloat16 g_H [NTOK * C];   // expert hidden (compact, bf16)
__device__ float g_X [NTOK * C];           // Y (expert output, fp32, compact)
__device__ float g_G1[NTOK * C];           // gate hidden (fp32)
__device__ uint32_t g_gw1b[K2C * C];       // gate w1 bf16, k-pair packed
__device__ uint32_t g_ew1b[NE * K2C * C];  // expert w1 bf16 packed
__device__ uint32_t g_ew2b[NE * K2C * C];  // expert w2 bf16 packed
__device__ int   g_top[NTOK];
__device__ float g_gv[NTOK];
__device__ int   g_perm[NTOK];
__device__ int   g_tok2g[NTOK];
__device__ int   g_counts[NE];
__device__ int   g_offsets[NE + 1];
__device__ int   g_fill[NE];
__device__ int   g_nfix;
__device__ int   g_fix[NTOK];

// ---------------------------------------------------------------------------
// Helpers
// ---------------------------------------------------------------------------
__device__ __forceinline__ float gelu_tanh(float x) {
    float x3 = x * x * x;
    return 0.5f * x * (1.0f + tanhf(0.7978845608028654f * x + 0.035677408136300125f * x3));
}

__device__ __forceinline__ void cp_async16(uint32_t smem_dst, const void* gsrc, bool valid) {
    int sz = valid ? 16 : 0;
    asm volatile("cp.async.cg.shared.global [%0], [%1], 16, %2;\n"
                 :: "r"(smem_dst), "l"(gsrc), "r"(sz));
}
__device__ __forceinline__ void cp_commit() { asm volatile("cp.async.commit_group;\n"); }
__device__ __forceinline__ void cp_wait0()  { asm volatile("cp.async.wait_group 0;\n"); }

__device__ __forceinline__ void mma_bf16(float* c, const uint32_t* a, const uint32_t* b) {
    asm volatile(
        "mma.sync.aligned.m16n8k16.row.col.f32.bf16.bf16.f32 "
        "{%0,%1,%2,%3},{%4,%5,%6,%7},{%8,%9},{%0,%1,%2,%3};\n"
        : "+f"(c[0]), "+f"(c[1]), "+f"(c[2]), "+f"(c[3])
        : "r"(a[0]), "r"(a[1]), "r"(a[2]), "r"(a[3]), "r"(b[0]), "r"(b[1]));
}

__device__ __forceinline__ uint32_t pack_bf16x2(float v0, float v1) {
    uint32_t r;
    asm("cvt.rn.bf16x2.f32 %0, %1, %2;" : "=r"(r) : "f"(v1), "f"(v0));
    return r;
}

// grid-stride copy over 1024-float4 windows (cnt4 % 1024 == 0), stride NB_COPY
__device__ __forceinline__ void do_copy(int cblk, int tid,
                                        const float4* __restrict__ s,
                                        float4* __restrict__ d, int cnt4) {
    size_t i = (size_t)cblk * 1024 + tid;
    const size_t stride = (size_t)NB_COPY * 1024;
    for (; i < (size_t)cnt4; i += stride) {
        float4 v0 = s[i];
        float4 v1 = s[i + 256];
        float4 v2 = s[i + 512];
        float4 v3 = s[i + 768];
        d[i]       = v0;
        d[i + 256] = v1;
        d[i + 512] = v2;
        d[i + 768] = v3;
    }
}

// ---------------------------------------------------------------------------
// 1. prep: token transpose (hi/lo bf16) + gate-w1 pack (plain bf16)
// ---------------------------------------------------------------------------
__global__ void prep_k(const float* __restrict__ s32, const float* __restrict__ gw1) {
    int blk = blockIdx.x;
    int tx = threadIdx.x, ty = threadIdx.y;   // (32, 8)

    if (blk < 6144) {
        __shared__ float tile[32][33];
        int bx = blk & 31;
        int t  = blk >> 5;
        int by = t % 24;
        int bz = t / 24;
        int c0 = by * 32, hw0 = bx * 32;
        if (blk == 0 && ty == 0 && tx < NE + 1) {
            if (tx < NE) g_counts[tx] = 0;
            else g_nfix = 0;
        }
        const float* src = s32 + ((size_t)bz * C + c0) * 1024 + hw0;
        #pragma unroll
        for (int j = 0; j < 32; j += 8)
            tile[ty + j][tx] = src[(ty + j) * 1024 + tx];
        __syncthreads();
        size_t dbase = ((size_t)(bz * 1024 + hw0)) * C + c0;
        #pragma unroll
        for (int j = 0; j < 32; j += 8) {
            float x = tile[tx][ty + j];
            __nv_bfloat16 h = __float2bfloat16(x);
            float r = x - __bfloat162float(h);
            size_t idx = dbase + (size_t)(ty + j) * C + tx;
            g_Xb[idx] = h;
            g_Xl[idx] = __float2bfloat16(r);
        }
    } else {
        // gate w1 pack (plain bf16): [K2C][C] words
        int tid = ty * 32 + tx;
        const int total = K2C * C;
        for (int w = (blk - 6144) * 256 + tid; w < total; w += 256 * 256) {
            int k2 = w / C, n = w - k2 * C;
            float w0 = gw1[(size_t)(2 * k2) * C + n];
            float w1 = gw1[(size_t)(2 * k2 + 1) * C + n];
            g_gw1b[w] = pack_bf16x2(w0, w1);
        }
    }
}

// ---------------------------------------------------------------------------
// bf16 GEMM: block 128x128, 8 warps (2m x 4n) of 64x32, 256 threads.
//   MODE 0: G1 = gelu(Xb@gw1+b1)          -> g_G1 (fp32)
//   MODE 1: H  = gelu(gather(Xb)@ew1+b1)  -> g_H (bf16)
//   MODE 2: Y  = (H@ew2+b2)*gate_val      -> g_X (fp32)
// Blocks [0, NB_COPY) run the passthrough copy (wave-1 co-resident overlap).
// MODE 0: blocks [NB_COPY, nbPre) pack expert weights (overlaps gate GEMM).
// ---------------------------------------------------------------------------
template <int MODE>
__launch_bounds__(256)
__global__ void mma_gemm_k(const float* __restrict__ Ball,
                           const float4* __restrict__ csrc, float4* __restrict__ cdst, int cnt4,
                           const float* __restrict__ cvt1, const float* __restrict__ cvt2,
                           int nbPre) {
    const int blk = blockIdx.x;
    const int tid = threadIdx.x;

    if (blk < NB_COPY) { do_copy(blk, tid, csrc, cdst, cnt4); return; }

    if (MODE == 0 && blk < nbPre) {
        const int cb = blk - NB_COPY;
        const int WCNT = NE * K2C * C;
        for (int w = cb * 256 + tid; w < 2 * WCNT; w += NB_CONV * 256) {
            int wi = w;
            const float* src; uint32_t* dst;
            if (wi < WCNT) { src = cvt1; dst = g_ew1b; }
            else           { wi -= WCNT; src = cvt2; dst = g_ew2b; }
            int k2g = wi / C, n = wi - k2g * C;
            float w0 = src[(size_t)(2 * k2g) * C + n];
            float w1 = src[(size_t)(2 * k2g + 1) * C + n];
            dst[wi] = pack_bf16x2(w0, w1);
        }
        return;
    }

    // ---- GEMM tile mapping ----------------------------------------------
    const int gblk = blk - nbPre;
    int e, bx, by;
    if (MODE == 0) { e = 0; bx = gblk & (MT - 1); by = gblk >> 6; }
    else { e = gblk / (MT * NT); int r = gblk - e * (MT * NT); bx = r & (MT - 1); by = r >> 6; }

    int base, cnt;
    if (MODE == 0) { base = 0; cnt = NTOK; }
    else           { base = g_offsets[e]; cnt = g_offsets[e + 1] - base; }

    const int m0 = bx * TBM;
    if (m0 >= cnt) return;
    const int n0 = by * TBN;

    const uint32_t* Wh = (MODE == 0) ? g_gw1b
                        : (MODE == 1) ? (g_ew1b + (size_t)e * K2C * C)
                                      : (g_ew2b + (size_t)e * K2C * C);
    const float* bias  = Ball + ((MODE == 0) ? 0 : e * C);

    extern __shared__ uint32_t sm[];
    uint32_t* AhB = sm;
    uint32_t* BhB = sm + 2 * A_STAGE_W;
    const uint32_t sAh = (uint32_t)__cvta_generic_to_shared(AhB);
    const uint32_t sBh = (uint32_t)__cvta_generic_to_shared(BhB);

    const int wid  = tid >> 5;
    const int lane = tid & 31;
    const int g    = lane >> 2;
    const int tig  = lane & 3;
    const int mW   = (wid & 1) * 64;     // m 0-63 or 64-127
    const int nW   = (wid >> 1) * 32;    // n slice of 32 per warp pair-group

    // A loader: 2 x 16B chunks / thread / stage
    const __nv_bfloat16* Asrc = (MODE == 2) ? g_H : g_Xb;
    const uint8_t* srcA[2]; uint32_t dstA[2]; bool vA[2];
    #pragma unroll
    for (int i = 0; i < 2; i++) {
        int q = tid + i * 256;
        int chunk = q >> 7;          // 0..3
        int row   = q & 127;
        int m = m0 + row;
        bool v = (m < cnt);
        int ar = 0;
        if (v) {
            if      (MODE == 1) ar = g_perm[base + m];
            else if (MODE == 2) ar = base + m;
            else                ar = m;
        }
        srcA[i]  = (const uint8_t*)Asrc + (size_t)ar * C * 2 + chunk * 16;
        dstA[i]  = (uint32_t)(row * AS_W + chunk * 4) * 4u;
        vA[i] = v;
    }
    // B loader: 2 x 16B chunks / thread / stage
    size_t srcBoff[2]; uint32_t dstB[2];
    #pragma unroll
    for (int i = 0; i < 2; i++) {
        int q = tid + i * 256;
        int k2r = q >> 5;            // 0..15
        int c   = q & 31;            // 0..31
        srcBoff[i] = (size_t)k2r * C + n0 + c * 4;
        dstB[i]    = (uint32_t)(k2r * BS_W + c * 4) * 4u;
    }

    float acc[4][4][4];
    #pragma unroll
    for (int mt = 0; mt < 4; mt++)
        #pragma unroll
        for (int nt = 0; nt < 4; nt++)
            #pragma unroll
            for (int r = 0; r < 4; r++) acc[mt][nt][r] = 0.f;

    const int T = C / TBK;  // 24

    // prologue: stage 0
    #pragma unroll
    for (int i = 0; i < 2; i++) cp_async16(sAh + dstA[i], srcA[i], vA[i]);
    #pragma unroll
    for (int i = 0; i < 2; i++) cp_async16(sBh + dstB[i], Wh + srcBoff[i], true);
    cp_commit();

    for (int t = 0; t < T; t++) {
        const int cur = t & 1;
        cp_wait0();
        __syncthreads();

        if (t + 1 < T) {
            const int nxt = cur ^ 1;
            const int kb = (t + 1) * (TBK * 2);                 // bytes into A rows
            const size_t kw = (size_t)(t + 1) * (TBK / 2) * C;  // words into W
            #pragma unroll
            for (int i = 0; i < 2; i++)
                cp_async16(sAh + nxt * (A_STAGE_W * 4) + dstA[i], srcA[i] + kb, vA[i]);
            #pragma unroll
            for (int i = 0; i < 2; i++)
                cp_async16(sBh + nxt * (B_STAGE_W * 4) + dstB[i], Wh + srcBoff[i] + kw, true);
            cp_commit();
        }

        const uint32_t* Ahc = AhB + cur * A_STAGE_W;
        const uint32_t* Bhc = BhB + cur * B_STAGE_W;

        #pragma unroll
        for (int ks = 0; ks < 2; ks++) {
            const int k8 = ks * 8;
            uint32_t bh[4][2];
            #pragma unroll
            for (int nt = 0; nt < 4; nt++) {
                const int n = nW + nt * 8 + g;
                bh[nt][0] = Bhc[(k8 + tig)     * BS_W + n];
                bh[nt][1] = Bhc[(k8 + tig + 4) * BS_W + n];
            }
            #pragma unroll
            for (int mt = 0; mt < 4; mt++) {
                const int r0 = mW + mt * 16 + g;
                uint32_t ah[4];
                ah[0] = Ahc[ r0      * AS_W + k8 + tig];
                ah[1] = Ahc[(r0 + 8) * AS_W + k8 + tig];
                ah[2] = Ahc[ r0      * AS_W + k8 + tig + 4];
                ah[3] = Ahc[(r0 + 8) * AS_W + k8 + tig + 4];
                #pragma unroll
                for (int nt = 0; nt < 4; nt++)
                    mma_bf16(acc[mt][nt], ah, bh[nt]);
            }
        }
        __syncthreads();
    }

    // ---- epilogue --------------------------------------------------------
    #pragma unroll
    for (int mt = 0; mt < 4; mt++) {
        #pragma unroll
        for (int half = 0; half < 2; half++) {
            const int m = m0 + mW + mt * 16 + g + half * 8;
            if (m >= cnt) continue;
            float gv = 1.f;
            if (MODE == 2) gv = g_gv[g_perm[base + m]];
            #pragma unroll
            for (int nt = 0; nt < 4; nt++) {
                const int col = n0 + nW + nt * 8 + tig * 2;
                float2 bv = *(const float2*)(bias + col);
                float v0 = acc[mt][nt][half * 2 + 0] + bv.x;
                float v1 = acc[mt][nt][half * 2 + 1] + bv.y;
                if (MODE == 0) {
                    float* orow = g_G1 + (size_t)m * C;
                    *(float2*)(orow + col) = make_float2(gelu_tanh(v0), gelu_tanh(v1));
                } else if (MODE == 1) {
                    __nv_bfloat162* hrow = (__nv_bfloat162*)(g_H + (size_t)(base + m) * C);
                    hrow[col >> 1] = __floats2bfloat162_rn(gelu_tanh(v0), gelu_tanh(v1));
                } else {
                    float* orow = g_X + (size_t)(base + m) * C;
                    *(float2*)(orow + col) = make_float2(v0 * gv, v1 * gv);
                }
            }
        }
    }
}

// ---------------------------------------------------------------------------
// 3. logits from G1 (bf16-noised). Confident tokens finalize; near-ties go to
//    the fix list for exact fp32 recompute.
// ---------------------------------------------------------------------------
__global__ void gate_k(const float* __restrict__ w2, const float* __restrict__ b2) {
    int warp = (blockIdx.x * blockDim.x + threadIdx.x) >> 5;
    int lane = threadIdx.x & 31;
    if (warp >= NTOK) return;
    const float* g = g_G1 + (size_t)warp * C;
    float l0 = 0.f, l1 = 0.f, l2 = 0.f, l3 = 0.f;
    for (int c = lane; c < C; c += 32) {
        float x = g[c];
        float4 wv = *(const float4*)(w2 + c * 4);
        l0 = fmaf(x, wv.x, l0);
        l1 = fmaf(x, wv.y, l1);
        l2 = fmaf(x, wv.z, l2);
        l3 = fmaf(x, wv.w, l3);
    }
    #pragma unroll
    for (int o = 16; o; o >>= 1) {
        l0 += __shfl_xor_sync(0xffffffffu, l0, o);
        l1 += __shfl_xor_sync(0xffffffffu, l1, o);
        l2 += __shfl_xor_sync(0xffffffffu, l2, o);
        l3 += __shfl_xor_sync(0xffffffffu, l3, o);
    }
    if (lane == 0) {
        l0 += b2[0]; l1 += b2[1]; l2 += b2[2]; l3 += b2[3];
        float m = l0; int idx = 0;
        if (l1 > m) { m = l1; idx = 1; }   // strict '>' keeps first max (jnp.argmax)
        if (l2 > m) { m = l2; idx = 2; }
        if (l3 > m) { m = l3; idx = 3; }
        float m2 = -3.0e38f;
        if (idx != 0 && l0 > m2) m2 = l0;
        if (idx != 1 && l1 > m2) m2 = l1;
        if (idx != 2 && l2 > m2) m2 = l2;
        if (idx != 3 && l3 > m2) m2 = l3;
        float thresh = 0.02f + 0.02f * fabsf(m);   // >> bf16 logit noise bound
        if (m - m2 > thresh) {
            float s = expf(l0 - m) + expf(l1 - m) + expf(l2 - m) + expf(l3 - m);
            g_top[warp] = idx;
            g_gv[warp]  = 1.0f / s;
            atomicAdd(&g_counts[idx], 1);
        } else {
            int p = atomicAdd(&g_nfix, 1);
            g_fix[p] = warp;
        }
    }
}

// ---------------------------------------------------------------------------
// 3b. exact fp32 re-routing for near-tie tokens (x reconstructed from Xb+Xl).
// One block processes fix-list entries with grid stride. Deterministic reduce.
// ---------------------------------------------------------------------------
__global__ void fixup_k(const float* __restrict__ gw1, const float* __restrict__ gb1,
                        const float* __restrict__ gw2, const float* __restrict__ gb2) {
    __shared__ float xs[C];
    __shared__ float wpart[8][4];
    const int tid = threadIdx.x;      // 256
    const int nfix = g_nfix;
    for (int i = blockIdx.x; i < nfix; i += gridDim.x) {
        const int n = g_fix[i];
        for (int c = tid; c < C; c += 256)
            xs[c] = __bfloat162float(g_Xb[(size_t)n * C + c])
                  + __bfloat162float(g_Xl[(size_t)n * C + c]);
        __syncthreads();
        float a0 = gb1[tid], a1 = gb1[tid + 256], a2 = gb1[tid + 512];
        for (int k = 0; k < C; k++) {
            float xv = xs[k];
            const float* wr = gw1 + (size_t)k * C;
            a0 = fmaf(xv, wr[tid], a0);
            a1 = fmaf(xv, wr[tid + 256], a1);
            a2 = fmaf(xv, wr[tid + 512], a2);
        }
        float p0 = 0.f, p1 = 0.f, p2 = 0.f, p3 = 0.f;
        float hv[3] = { gelu_tanh(a0), gelu_tanh(a1), gelu_tanh(a2) };
        #pragma unroll
        for (int r = 0; r < 3; r++) {
            float4 wv = *(const float4*)(gw2 + (size_t)(tid + r * 256) * 4);
            p0 = fmaf(hv[r], wv.x, p0);
            p1 = fmaf(hv[r], wv.y, p1);
            p2 = fmaf(hv[r], wv.z, p2);
            p3 = fmaf(hv[r], wv.w, p3);
        }
        #pragma unroll
        for (int o = 16; o; o >>= 1) {
            p0 += __shfl_xor_sync(0xffffffffu, p0, o);
            p1 += __shfl_xor_sync(0xffffffffu, p1, o);
            p2 += __shfl_xor_sync(0xffffffffu, p2, o);
            p3 += __shfl_xor_sync(0xffffffffu, p3, o);
        }
        if ((tid & 31) == 0) {
            wpart[tid >> 5][0] = p0; wpart[tid >> 5][1] = p1;
            wpart[tid >> 5][2] = p2; wpart[tid >> 5][3] = p3;
        }
        __syncthreads();
        if (tid == 0) {
            float l0 = gb2[0], l1 = gb2[1], l2 = gb2[2], l3 = gb2[3];
            #pragma unroll
            for (int w = 0; w < 8; w++) {      // fixed order -> deterministic
                l0 += wpart[w][0]; l1 += wpart[w][1];
                l2 += wpart[w][2]; l3 += wpart[w][3];
            }
            float m = l0; int idx = 0;
            if (l1 > m) { m = l1; idx = 1; }
            if (l2 > m) { m = l2; idx = 2; }
            if (l3 > m) { m = l3; idx = 3; }
            float s = expf(l0 - m) + expf(l1 - m) + expf(l2 - m) + expf(l3 - m);
            g_top[n] = idx;
            g_gv[n]  = 1.0f / s;
            atomicAdd(&g_counts[idx], 1);
        }
        __syncthreads();
    }
}

// ---------------------------------------------------------------------------
// 4. tiny exclusive scan + reset fill cursors
// ---------------------------------------------------------------------------
__global__ void scan_k() {
    if (threadIdx.x == 0) {
        int s = 0;
        #pragma unroll
        for (int e = 0; e < NE; e++) {
            g_offsets[e] = s;
            s += g_counts[e];
            g_fill[e] = 0;
        }
        g_offsets[NE] = s;
    }
}

// ---------------------------------------------------------------------------
// 5. build permutation (token -> compact position, grouped by expert)
// ---------------------------------------------------------------------------
__global__ void perm_k() {
    int n = blockIdx.x * blockDim.x + threadIdx.x;
    if (n >= NTOK) return;
    int e = g_top[n];
    int pos = atomicAdd(&g_fill[e], 1);
    int gg = g_offsets[e] + pos;
    g_perm[gg]  = n;
    g_tok2g[n]  = gg;
}

// ---------------------------------------------------------------------------
// 8. coalesced scatter back to BCHW + residual
// ---------------------------------------------------------------------------
__global__ void scatter_k(const float* __restrict__ s32, float* __restrict__ out32) {
    __shared__ float tile[32][33];
    int b = blockIdx.z, c0 = blockIdx.y * 32, hw0 = blockIdx.x * 32;
    int tx = threadIdx.x, ty = threadIdx.y;   // (32, 8)
    for (int t = ty; t < 32; t += 8) {
        int n = b * 1024 + hw0 + t;
        int gg = g_tok2g[n];
        tile[t][tx] = g_X[(size_t)gg * C + c0 + tx];
    }
    __syncthreads();
    int ibase = b * (C * 1024) + hw0;
    #pragma unroll
    for (int j = 0; j < 4; j++) {
        int c = c0 + ty + 8 * j;
        int idx = ibase + c * 1024 + tx;
        out32[idx] = tile[tx][ty + 8 * j] + s32[idx];
    }
}

// ---------------------------------------------------------------------------
// launch
// ---------------------------------------------------------------------------
extern "C" void kernel_launch(void* const* d_in, const int* in_sizes, int n_in,
                              void* d_out, int out_size) {
    const float* s4  = (const float*)d_in[0];
    const float* s8  = (const float*)d_in[1];
    const float* s16 = (const float*)d_in[2];
    const float* s32 = (const float*)d_in[3];
    const float* gw1 = (const float*)d_in[4];
    const float* gb1 = (const float*)d_in[5];
    const float* gw2 = (const float*)d_in[6];
    const float* gb2 = (const float*)d_in[7];
    const float* ew1 = (const float*)d_in[8];
    const float* eb1 = (const float*)d_in[9];
    const float* ew2 = (const float*)d_in[10];
    const float* eb2 = (const float*)d_in[11];
    float* out = (float*)d_out;

    // prep: token transpose (hi/lo bf16) + gate w1 pack
    prep_k<<<6144 + 256, dim3(32, 8)>>>(s32, gw1);

    // gate hidden (plain bf16) + s4 copy + expert weight pack, one launch (R6 layout)
    mma_gemm_k<0><<<NB_COPY + NB_CONV + MT * NT, 256, SMEM_GEMM_BYTES>>>(
        gb1, (const float4*)s4, (float4*)out, S4_ELEMS / 4, ew1, ew2, NB_COPY + NB_CONV);

    // routing: confident tokens finalize in gate_k; near-ties re-routed in fp32
    gate_k<<<(NTOK * 32) / 256, 256>>>(gw2, gb2);
    fixup_k<<<148, 256>>>(gw1, gb1, gw2, gb2);
    scan_k<<<1, 1>>>();
    perm_k<<<NTOK / 256, 256>>>();

    // expert up (bf16) + s8 copy
    mma_gemm_k<1><<<NB_COPY + MT * NT * NE, 256, SMEM_GEMM_BYTES>>>(
        eb1, (const float4*)s8, (float4*)(out + OFF_S8), S8_ELEMS / 4,
        nullptr, nullptr, NB_COPY);

    // expert down (bf16) + s16 copy
    mma_gemm_k<2><<<NB_COPY + MT * NT * NE, 256, SMEM_GEMM_BYTES>>>(
        eb2, (const float4*)s16, (float4*)(out + OFF_S16), S16_ELEMS / 4,
        nullptr, nullptr, NB_COPY);

    // scatter + residual into out32
    scatter_k<<<dim3(32, 24, 8), dim3(32, 8)>>>(s32, out + OFF_S32);
}

// round 15
// speedup vs baseline: 2.2889x; 2.2889x over previous
#include <cuda_runtime.h>
#include <cuda_bf16.h>
#include <math.h>
#include <stdint.h>

// ---------------------------------------------------------------------------
// Problem constants
// ---------------------------------------------------------------------------
#define NTOK 8192           // 8 * 32 * 32 tokens at stride 32
#define C    768            // channels
#define K2C  384            // C/2 (k-pair rows of packed weights)
#define NE   4              // experts

#define S4_ELEMS  50331648  // 8*96*256*256
#define S8_ELEMS  25165824  // 8*192*128*128
#define S16_ELEMS 12582912  // 8*384*64*64
#define OFF_S8   50331648
#define OFF_S16  75497472
#define OFF_S32  88080384

// GEMM tiling (bf16 m16n8k16, block 128x128, 8 warps of 64x32, 256 threads)
#define TBM 128
#define TBN 128
#define TBK 32              // k per smem stage (2 x k16 mma steps)
#define AS_W 20             // u32 words per A smem row (32 bf16 data + pad)
#define BS_W 136            // u32 words per B smem row (128 data + 8 pad)
#define A_STAGE_W (TBM * AS_W)        // 2560 words
#define B_STAGE_W ((TBK/2) * BS_W)    // 2176 words
#define SMEM_PLAIN_BYTES ((2*A_STAGE_W + 2*B_STAGE_W) * 4)          // 37888
#define SMEM_SPLIT_BYTES ((4*A_STAGE_W + 4*B_STAGE_W) * 4)          // 75776

#define MT (NTOK / TBM)     // 64 m-tiles
#define NT (C / TBN)        // 6  n-tiles
#define NB_COPY 148         // copy blocks PREPENDED per GEMM launch (proven R6/R8)
#define NB_CONV 256         // expert-weight convert blocks (gate launch only)

// ---------------------------------------------------------------------------
// Scratch (device globals: no allocation allowed)
// ---------------------------------------------------------------------------
__device__ __nv_bfloat16 g_Xb[NTOK * C];   // tokens hi bf16
__device__ __nv_bfloat16 g_Xl[NTOK * C];   // tokens lo bf16 (residual)
__device__ __nv_bfloat16 g_H [NTOK * C];   // expert hidden (compact, bf16)
__device__ float g_X [NTOK * C];           // Y (expert output, fp32, compact)
__device__ float g_G1[NTOK * C];           // gate hidden (fp32)
__device__ uint32_t g_gw1h[K2C * C];       // gate w1 hi, k-pair packed bf16x2
__device__ uint32_t g_gw1l[K2C * C];       // gate w1 lo (for fixup GEMM)
__device__ uint32_t g_ew1b[NE * K2C * C];  // expert w1 bf16 packed
__device__ uint32_t g_ew2b[NE * K2C * C];  // expert w2 bf16 packed
__device__ int   g_top[NTOK];
__device__ float g_gv[NTOK];
__device__ int   g_perm[NTOK];
__device__ int   g_tok2g[NTOK];
__device__ int   g_counts[NE];
__device__ int   g_offsets[NE + 1];
__device__ int   g_fill[NE];
__device__ int   g_nfix;
__device__ int   g_fix[NTOK];

// ---------------------------------------------------------------------------
// Helpers
// ---------------------------------------------------------------------------
__device__ __forceinline__ float gelu_tanh(float x) {
    float x3 = x * x * x;
    return 0.5f * x * (1.0f + tanhf(0.7978845608028654f * x + 0.035677408136300125f * x3));
}

__device__ __forceinline__ void cp_async16(uint32_t smem_dst, const void* gsrc, bool valid) {
    int sz = valid ? 16 : 0;
    asm volatile("cp.async.cg.shared.global [%0], [%1], 16, %2;\n"
                 :: "r"(smem_dst), "l"(gsrc), "r"(sz));
}
__device__ __forceinline__ void cp_commit() { asm volatile("cp.async.commit_group;\n"); }
__device__ __forceinline__ void cp_wait0()  { asm volatile("cp.async.wait_group 0;\n"); }

__device__ __forceinline__ void mma_bf16(float* c, const uint32_t* a, const uint32_t* b) {
    asm volatile(
        "mma.sync.aligned.m16n8k16.row.col.f32.bf16.bf16.f32 "
        "{%0,%1,%2,%3},{%4,%5,%6,%7},{%8,%9},{%0,%1,%2,%3};\n"
        : "+f"(c[0]), "+f"(c[1]), "+f"(c[2]), "+f"(c[3])
        : "r"(a[0]), "r"(a[1]), "r"(a[2]), "r"(a[3]), "r"(b[0]), "r"(b[1]));
}

__device__ __forceinline__ uint32_t pack_bf16x2(float v0, float v1) {
    uint32_t r;
    asm("cvt.rn.bf16x2.f32 %0, %1, %2;" : "=r"(r) : "f"(v1), "f"(v0));
    return r;
}

// grid-stride copy over 1024-float4 windows (cnt4 % 1024 == 0), stride NB_COPY
__device__ __forceinline__ void do_copy(int cblk, int tid,
                                        const float4* __restrict__ s,
                                        float4* __restrict__ d, int cnt4) {
    size_t i = (size_t)cblk * 1024 + tid;
    const size_t stride = (size_t)NB_COPY * 1024;
    for (; i < (size_t)cnt4; i += stride) {
        float4 v0 = s[i];
        float4 v1 = s[i + 256];
        float4 v2 = s[i + 512];
        float4 v3 = s[i + 768];
        d[i]       = v0;
        d[i + 256] = v1;
        d[i + 512] = v2;
        d[i + 768] = v3;
    }
}

// ---------------------------------------------------------------------------
// 1. prep: token transpose (hi/lo bf16) + gate-w1 split pack (hi + lo)
// ---------------------------------------------------------------------------
__global__ void prep_k(const float* __restrict__ s32, const float* __restrict__ gw1) {
    int blk = blockIdx.x;
    int tx = threadIdx.x, ty = threadIdx.y;   // (32, 8)

    if (blk < 6144) {
        __shared__ float tile[32][33];
        int bx = blk & 31;
        int t  = blk >> 5;
        int by = t % 24;
        int bz = t / 24;
        int c0 = by * 32, hw0 = bx * 32;
        if (blk == 0 && ty == 0 && tx < NE + 1) {
            if (tx < NE) g_counts[tx] = 0;
            else g_nfix = 0;
        }
        const float* src = s32 + ((size_t)bz * C + c0) * 1024 + hw0;
        #pragma unroll
        for (int j = 0; j < 32; j += 8)
            tile[ty + j][tx] = src[(ty + j) * 1024 + tx];
        __syncthreads();
        size_t dbase = ((size_t)(bz * 1024 + hw0)) * C + c0;
        #pragma unroll
        for (int j = 0; j < 32; j += 8) {
            float x = tile[tx][ty + j];
            __nv_bfloat16 h = __float2bfloat16(x);
            float r = x - __bfloat162float(h);
            size_t idx = dbase + (size_t)(ty + j) * C + tx;
            g_Xb[idx] = h;
            g_Xl[idx] = __float2bfloat16(r);
        }
    } else {
        // gate w1 split pack: [K2C][C] words, hi + lo
        int tid = ty * 32 + tx;
        const int total = K2C * C;
        for (int w = (blk - 6144) * 256 + tid; w < total; w += 256 * 256) {
            int k2 = w / C, n = w - k2 * C;
            float w0 = gw1[(size_t)(2 * k2) * C + n];
            float w1 = gw1[(size_t)(2 * k2 + 1) * C + n];
            float h0 = __bfloat162float(__float2bfloat16(w0));
            float h1 = __bfloat162float(__float2bfloat16(w1));
            g_gw1h[w] = pack_bf16x2(h0, h1);
            g_gw1l[w] = pack_bf16x2(w0 - h0, w1 - h1);
        }
    }
}

// ---------------------------------------------------------------------------
// bf16 GEMM: block 128x128, 8 warps (2m x 4n) of 64x32, 256 threads.
//   MODE 0 (plain): G1 = gelu(Xb@gw1h+b1)  -> g_G1 (fp32); hosts copy+conv blocks
//   MODE 1 (plain): H  = gelu(gather(Xb)@ew1+b1) -> g_H (bf16)
//   MODE 2 (plain): Y  = (H@ew2+b2)*gate_val     -> g_X (fp32)
//   MODE 3 (split): exact hidden for fix-list tokens -> scatter to g_G1 rows
// Blocks [0, NB_COPY) run the passthrough copy (MODE 0/1/2).
// MODE 0: blocks [NB_COPY, nbPre) pack expert weights (overlaps gate GEMM).
// ---------------------------------------------------------------------------
template <int MODE>
__launch_bounds__(256)
__global__ void mma_gemm_k(const float* __restrict__ Ball,
                           const float4* __restrict__ csrc, float4* __restrict__ cdst, int cnt4,
                           const float* __restrict__ cvt1, const float* __restrict__ cvt2,
                           int nbPre) {
    constexpr bool SPLIT = (MODE == 3);
    const int blk = blockIdx.x;
    const int tid = threadIdx.x;

    if (MODE != 3 && blk < NB_COPY) { do_copy(blk, tid, csrc, cdst, cnt4); return; }

    if (MODE == 0 && blk < nbPre) {
        const int cb = blk - NB_COPY;
        const int WCNT = NE * K2C * C;
        for (int w = cb * 256 + tid; w < 2 * WCNT; w += NB_CONV * 256) {
            int wi = w;
            const float* src; uint32_t* dst;
            if (wi < WCNT) { src = cvt1; dst = g_ew1b; }
            else           { wi -= WCNT; src = cvt2; dst = g_ew2b; }
            int k2g = wi / C, n = wi - k2g * C;
            float w0 = src[(size_t)(2 * k2g) * C + n];
            float w1 = src[(size_t)(2 * k2g + 1) * C + n];
            dst[wi] = pack_bf16x2(w0, w1);
        }
        return;
    }

    // ---- GEMM tile mapping ----------------------------------------------
    const int gblk = blk - ((MODE == 3) ? 0 : nbPre);
    int e, bx, by;
    if (MODE == 0 || MODE == 3) { e = 0; bx = gblk & (MT - 1); by = gblk >> 6; }
    else { e = gblk / (MT * NT); int r = gblk - e * (MT * NT); bx = r & (MT - 1); by = r >> 6; }

    int base, cnt;
    if      (MODE == 0) { base = 0; cnt = NTOK; }
    else if (MODE == 3) { base = 0; cnt = g_nfix; }
    else                { base = g_offsets[e]; cnt = g_offsets[e + 1] - base; }

    const int m0 = bx * TBM;
    if (m0 >= cnt) return;
    const int n0 = by * TBN;

    const uint32_t* Wh = (MODE == 0 || MODE == 3) ? g_gw1h
                        : (MODE == 1) ? (g_ew1b + (size_t)e * K2C * C)
                                      : (g_ew2b + (size_t)e * K2C * C);
    const uint32_t* Wl = g_gw1l;   // only used when SPLIT
    const float* bias  = Ball + ((MODE == 1 || MODE == 2) ? e * C : 0);

    extern __shared__ uint32_t sm[];
    uint32_t* AhB = sm;
    uint32_t* AlB = sm + 2 * A_STAGE_W;
    uint32_t* BhB = sm + (SPLIT ? 4 : 2) * A_STAGE_W;
    uint32_t* BlB = BhB + 2 * B_STAGE_W;
    const uint32_t sAh = (uint32_t)__cvta_generic_to_shared(AhB);
    const uint32_t sAl = (uint32_t)__cvta_generic_to_shared(AlB);
    const uint32_t sBh = (uint32_t)__cvta_generic_to_shared(BhB);
    const uint32_t sBl = (uint32_t)__cvta_generic_to_shared(BlB);

    const int wid  = tid >> 5;
    const int lane = tid & 31;
    const int g    = lane >> 2;
    const int tig  = lane & 3;
    const int mW   = (wid & 1) * 64;     // m 0-63 or 64-127
    const int nW   = (wid >> 1) * 32;    // n slice of 32 per warp pair-group

    // A loader: 2 x 16B chunks / thread / stage (per array)
    const __nv_bfloat16* Asrc = (MODE == 2) ? g_H : g_Xb;
    const uint8_t* srcA[2]; const uint8_t* srcAL[2]; uint32_t dstA[2]; bool vA[2];
    #pragma unroll
    for (int i = 0; i < 2; i++) {
        int q = tid + i * 256;
        int chunk = q >> 7;          // 0..3
        int row   = q & 127;
        int m = m0 + row;
        bool v = (m < cnt);
        int ar = 0;
        if (v) {
            if      (MODE == 1) ar = g_perm[base + m];
            else if (MODE == 2) ar = base + m;
            else if (MODE == 3) ar = g_fix[m];
            else                ar = m;
        }
        size_t boff = (size_t)ar * C * 2 + chunk * 16;
        srcA[i]  = (const uint8_t*)Asrc + boff;
        srcAL[i] = (const uint8_t*)g_Xl + boff;
        dstA[i]  = (uint32_t)(row * AS_W + chunk * 4) * 4u;
        vA[i] = v;
    }
    // B loader: 2 x 16B chunks / thread / stage
    size_t srcBoff[2]; uint32_t dstB[2];
    #pragma unroll
    for (int i = 0; i < 2; i++) {
        int q = tid + i * 256;
        int k2r = q >> 5;            // 0..15
        int c   = q & 31;            // 0..31
        srcBoff[i] = (size_t)k2r * C + n0 + c * 4;
        dstB[i]    = (uint32_t)(k2r * BS_W + c * 4) * 4u;
    }

    float acc[4][4][4];
    #pragma unroll
    for (int mt = 0; mt < 4; mt++)
        #pragma unroll
        for (int nt = 0; nt < 4; nt++)
            #pragma unroll
            for (int r = 0; r < 4; r++) acc[mt][nt][r] = 0.f;

    const int T = C / TBK;  // 24

    // prologue: stage 0
    #pragma unroll
    for (int i = 0; i < 2; i++) cp_async16(sAh + dstA[i], srcA[i], vA[i]);
    if (SPLIT)
        #pragma unroll
        for (int i = 0; i < 2; i++) cp_async16(sAl + dstA[i], srcAL[i], vA[i]);
    #pragma unroll
    for (int i = 0; i < 2; i++) cp_async16(sBh + dstB[i], Wh + srcBoff[i], true);
    if (SPLIT)
        #pragma unroll
        for (int i = 0; i < 2; i++) cp_async16(sBl + dstB[i], Wl + srcBoff[i], true);
    cp_commit();

    for (int t = 0; t < T; t++) {
        const int cur = t & 1;
        cp_wait0();
        __syncthreads();

        if (t + 1 < T) {
            const int nxt = cur ^ 1;
            const int kb = (t + 1) * (TBK * 2);                 // bytes into A rows
            const size_t kw = (size_t)(t + 1) * (TBK / 2) * C;  // words into W
            #pragma unroll
            for (int i = 0; i < 2; i++)
                cp_async16(sAh + nxt * (A_STAGE_W * 4) + dstA[i], srcA[i] + kb, vA[i]);
            if (SPLIT)
                #pragma unroll
                for (int i = 0; i < 2; i++)
                    cp_async16(sAl + nxt * (A_STAGE_W * 4) + dstA[i], srcAL[i] + kb, vA[i]);
            #pragma unroll
            for (int i = 0; i < 2; i++)
                cp_async16(sBh + nxt * (B_STAGE_W * 4) + dstB[i], Wh + srcBoff[i] + kw, true);
            if (SPLIT)
                #pragma unroll
                for (int i = 0; i < 2; i++)
                    cp_async16(sBl + nxt * (B_STAGE_W * 4) + dstB[i], Wl + srcBoff[i] + kw, true);
            cp_commit();
        }

        const uint32_t* Ahc = AhB + cur * A_STAGE_W;
        const uint32_t* Alc = AlB + cur * A_STAGE_W;
        const uint32_t* Bhc = BhB + cur * B_STAGE_W;
        const uint32_t* Blc = BlB + cur * B_STAGE_W;

        #pragma unroll
        for (int ks = 0; ks < 2; ks++) {
            const int k8 = ks * 8;
            uint32_t bh[4][2], bl[4][2];
            #pragma unroll
            for (int nt = 0; nt < 4; nt++) {
                const int n = nW + nt * 8 + g;
                bh[nt][0] = Bhc[(k8 + tig)     * BS_W + n];
                bh[nt][1] = Bhc[(k8 + tig + 4) * BS_W + n];
                if (SPLIT) {
                    bl[nt][0] = Blc[(k8 + tig)     * BS_W + n];
                    bl[nt][1] = Blc[(k8 + tig + 4) * BS_W + n];
                }
            }
            #pragma unroll
            for (int mt = 0; mt < 4; mt++) {
                const int r0 = mW + mt * 16 + g;
                uint32_t ah[4], al[4];
                ah[0] = Ahc[ r0      * AS_W + k8 + tig];
                ah[1] = Ahc[(r0 + 8) * AS_W + k8 + tig];
                ah[2] = Ahc[ r0      * AS_W + k8 + tig + 4];
                ah[3] = Ahc[(r0 + 8) * AS_W + k8 + tig + 4];
                if (SPLIT) {
                    al[0] = Alc[ r0      * AS_W + k8 + tig];
                    al[1] = Alc[(r0 + 8) * AS_W + k8 + tig];
                    al[2] = Alc[ r0      * AS_W + k8 + tig + 4];
                    al[3] = Alc[(r0 + 8) * AS_W + k8 + tig + 4];
                }
                #pragma unroll
                for (int nt = 0; nt < 4; nt++) {
                    mma_bf16(acc[mt][nt], ah, bh[nt]);
                    if (SPLIT) {
                        mma_bf16(acc[mt][nt], al, bh[nt]);
                        mma_bf16(acc[mt][nt], ah, bl[nt]);
                    }
                }
            }
        }
        __syncthreads();
    }

    // ---- epilogue --------------------------------------------------------
    #pragma unroll
    for (int mt = 0; mt < 4; mt++) {
        #pragma unroll
        for (int half = 0; half < 2; half++) {
            const int m = m0 + mW + mt * 16 + g + half * 8;
            if (m >= cnt) continue;
            float gv = 1.f;
            if (MODE == 2) gv = g_gv[g_perm[base + m]];
            int drow = 0;
            if      (MODE == 0) drow = m;
            else if (MODE == 3) drow = g_fix[m];
            #pragma unroll
            for (int nt = 0; nt < 4; nt++) {
                const int col = n0 + nW + nt * 8 + tig * 2;
                float2 bv = *(const float2*)(bias + col);
                float v0 = acc[mt][nt][half * 2 + 0] + bv.x;
                float v1 = acc[mt][nt][half * 2 + 1] + bv.y;
                if (MODE == 0 || MODE == 3) {
                    float* orow = g_G1 + (size_t)drow * C;
                    *(float2*)(orow + col) = make_float2(gelu_tanh(v0), gelu_tanh(v1));
                } else if (MODE == 1) {
                    __nv_bfloat162* hrow = (__nv_bfloat162*)(g_H + (size_t)(base + m) * C);
                    hrow[col >> 1] = __floats2bfloat162_rn(gelu_tanh(v0), gelu_tanh(v1));
                } else {
                    float* orow = g_X + (size_t)(base + m) * C;
                    *(float2*)(orow + col) = make_float2(v0 * gv, v1 * gv);
                }
            }
        }
    }
}

// ---------------------------------------------------------------------------
// 3. logits from G1 (bf16-noised). Confident tokens finalize; near-ties go to
//    the fix list for exact recompute via the MODE-3 GEMM.
// ---------------------------------------------------------------------------
__global__ void gate_k(const float* __restrict__ w2, const float* __restrict__ b2) {
    int warp = (blockIdx.x * blockDim.x + threadIdx.x) >> 5;
    int lane = threadIdx.x & 31;
    if (warp >= NTOK) return;
    const float* g = g_G1 + (size_t)warp * C;
    float l0 = 0.f, l1 = 0.f, l2 = 0.f, l3 = 0.f;
    for (int c = lane; c < C; c += 32) {
        float x = g[c];
        float4 wv = *(const float4*)(w2 + c * 4);
        l0 = fmaf(x, wv.x, l0);
        l1 = fmaf(x, wv.y, l1);
        l2 = fmaf(x, wv.z, l2);
        l3 = fmaf(x, wv.w, l3);
    }
    #pragma unroll
    for (int o = 16; o; o >>= 1) {
        l0 += __shfl_xor_sync(0xffffffffu, l0, o);
        l1 += __shfl_xor_sync(0xffffffffu, l1, o);
        l2 += __shfl_xor_sync(0xffffffffu, l2, o);
        l3 += __shfl_xor_sync(0xffffffffu, l3, o);
    }
    if (lane == 0) {
        l0 += b2[0]; l1 += b2[1]; l2 += b2[2]; l3 += b2[3];
        float m = l0; int idx = 0;
        if (l1 > m) { m = l1; idx = 1; }   // strict '>' keeps first max (jnp.argmax)
        if (l2 > m) { m = l2; idx = 2; }
        if (l3 > m) { m = l3; idx = 3; }
        float m2 = -3.0e38f;
        if (idx != 0 && l0 > m2) m2 = l0;
        if (idx != 1 && l1 > m2) m2 = l1;
        if (idx != 2 && l2 > m2) m2 = l2;
        if (idx != 3 && l3 > m2) m2 = l3;
        float thresh = 0.006f + 0.004f * fabsf(m);   // ~8 sigma of bf16 gap noise
        if (m - m2 > thresh) {
            float s = expf(l0 - m) + expf(l1 - m) + expf(l2 - m) + expf(l3 - m);
            g_top[warp] = idx;
            g_gv[warp]  = 1.0f / s;
            atomicAdd(&g_counts[idx], 1);
        } else {
            int p = atomicAdd(&g_nfix, 1);
            g_fix[p] = warp;
        }
    }
}

// ---------------------------------------------------------------------------
// 3b. finalize routing for fix-list tokens from their refreshed (exact) G1 rows
// ---------------------------------------------------------------------------
__global__ void fix_gate_k(const float* __restrict__ w2, const float* __restrict__ b2) {
    int i = (blockIdx.x * blockDim.x + threadIdx.x) >> 5;
    int lane = threadIdx.x & 31;
    if (i >= g_nfix) return;
    int n = g_fix[i];
    const float* g = g_G1 + (size_t)n * C;
    float l0 = 0.f, l1 = 0.f, l2 = 0.f, l3 = 0.f;
    for (int c = lane; c < C; c += 32) {
        float x = g[c];
        float4 wv = *(const float4*)(w2 + c * 4);
        l0 = fmaf(x, wv.x, l0);
        l1 = fmaf(x, wv.y, l1);
        l2 = fmaf(x, wv.z, l2);
        l3 = fmaf(x, wv.w, l3);
    }
    #pragma unroll
    for (int o = 16; o; o >>= 1) {
        l0 += __shfl_xor_sync(0xffffffffu, l0, o);
        l1 += __shfl_xor_sync(0xffffffffu, l1, o);
        l2 += __shfl_xor_sync(0xffffffffu, l2, o);
        l3 += __shfl_xor_sync(0xffffffffu, l3, o);
    }
    if (lane == 0) {
        l0 += b2[0]; l1 += b2[1]; l2 += b2[2]; l3 += b2[3];
        float m = l0; int idx = 0;
        if (l1 > m) { m = l1; idx = 1; }
        if (l2 > m) { m = l2; idx = 2; }
        if (l3 > m) { m = l3; idx = 3; }
        float s = expf(l0 - m) + expf(l1 - m) + expf(l2 - m) + expf(l3 - m);
        g_top[n] = idx;
        g_gv[n]  = 1.0f / s;
        atomicAdd(&g_counts[idx], 1);
    }
}

// ---------------------------------------------------------------------------
// 4. tiny exclusive scan + reset fill cursors
// ---------------------------------------------------------------------------
__global__ void scan_k() {
    if (threadIdx.x == 0) {
        int s = 0;
        #pragma unroll
        for (int e = 0; e < NE; e++) {
            g_offsets[e] = s;
            s += g_counts[e];
            g_fill[e] = 0;
        }
        g_offsets[NE] = s;
    }
}

// ---------------------------------------------------------------------------
// 5. build permutation (token -> compact position, grouped by expert)
// ---------------------------------------------------------------------------
__global__ void perm_k() {
    int n = blockIdx.x * blockDim.x + threadIdx.x;
    if (n >= NTOK) return;
    int e = g_top[n];
    int pos = atomicAdd(&g_fill[e], 1);
    int gg = g_offsets[e] + pos;
    g_perm[gg]  = n;
    g_tok2g[n]  = gg;
}

// ---------------------------------------------------------------------------
// 8. coalesced scatter back to BCHW + residual
// ---------------------------------------------------------------------------
__global__ void scatter_k(const float* __restrict__ s32, float* __restrict__ out32) {
    __shared__ float tile[32][33];
    int b = blockIdx.z, c0 = blockIdx.y * 32, hw0 = blockIdx.x * 32;
    int tx = threadIdx.x, ty = threadIdx.y;   // (32, 8)
    for (int t = ty; t < 32; t += 8) {
        int n = b * 1024 + hw0 + t;
        int gg = g_tok2g[n];
        tile[t][tx] = g_X[(size_t)gg * C + c0 + tx];
    }
    __syncthreads();
    int ibase = b * (C * 1024) + hw0;
    #pragma unroll
    for (int j = 0; j < 4; j++) {
        int c = c0 + ty + 8 * j;
        int idx = ibase + c * 1024 + tx;
        out32[idx] = tile[tx][ty + 8 * j] + s32[idx];
    }
}

// ---------------------------------------------------------------------------
// launch
// ---------------------------------------------------------------------------
extern "C" void kernel_launch(void* const* d_in, const int* in_sizes, int n_in,
                              void* d_out, int out_size) {
    const float* s4  = (const float*)d_in[0];
    const float* s8  = (const float*)d_in[1];
    const float* s16 = (const float*)d_in[2];
    const float* s32 = (const float*)d_in[3];
    const float* gw1 = (const float*)d_in[4];
    const float* gb1 = (const float*)d_in[5];
    const float* gw2 = (const float*)d_in[6];
    const float* gb2 = (const float*)d_in[7];
    const float* ew1 = (const float*)d_in[8];
    const float* eb1 = (const float*)d_in[9];
    const float* ew2 = (const float*)d_in[10];
    const float* eb2 = (const float*)d_in[11];
    float* out = (float*)d_out;

    cudaFuncSetAttribute(mma_gemm_k<3>, cudaFuncAttributeMaxDynamicSharedMemorySize, SMEM_SPLIT_BYTES);

    // prep: token transpose (hi/lo bf16) + gate w1 split pack
    prep_k<<<6144 + 256, dim3(32, 8)>>>(s32, gw1);

    // gate hidden (plain bf16) + s4 copy + expert weight pack, one launch (R6 layout)
    mma_gemm_k<0><<<NB_COPY + NB_CONV + MT * NT, 256, SMEM_PLAIN_BYTES>>>(
        gb1, (const float4*)s4, (float4*)out, S4_ELEMS / 4, ew1, ew2, NB_COPY + NB_CONV);

    // routing: confident tokens finalize; near-ties get exact split-bf16 recompute
    gate_k<<<(NTOK * 32) / 256, 256>>>(gw2, gb2);
    mma_gemm_k<3><<<MT * NT, 256, SMEM_SPLIT_BYTES>>>(
        gb1, nullptr, nullptr, 0, nullptr, nullptr, 0);
    fix_gate_k<<<(NTOK * 32) / 256, 256>>>(gw2, gb2);
    scan_k<<<1, 1>>>();
    perm_k<<<NTOK / 256, 256>>>();

    // expert up (bf16) + s8 copy
    mma_gemm_k<1><<<NB_COPY + MT * NT * NE, 256, SMEM_PLAIN_BYTES>>>(
        eb1, (const float4*)s8, (float4*)(out + OFF_S8), S8_ELEMS / 4,
        nullptr, nullptr, NB_COPY);

    // expert down (bf16) + s16 copy
    mma_gemm_k<2><<<NB_COPY + MT * NT * NE, 256, SMEM_PLAIN_BYTES>>>(
        eb2, (const float4*)s16, (float4*)(out + OFF_S16), S16_ELEMS / 4,
        nullptr, nullptr, NB_COPY);

    // scatter + residual into out32
    scatter_k<<<dim3(32, 24, 8), dim3(32, 8)>>>(s32, out + OFF_S32);
}

// round 16
// speedup vs baseline: 2.3074x; 1.0081x over previous
#include <cuda_runtime.h>
#include <cuda_bf16.h>
#include <math.h>
#include <stdint.h>

// ---------------------------------------------------------------------------
// Problem constants
// ---------------------------------------------------------------------------
#define NTOK 8192           // 8 * 32 * 32 tokens at stride 32
#define C    768            // channels
#define K2C  384            // C/2 (k-pair rows of packed weights)
#define NE   4              // experts

#define S4_ELEMS  50331648  // 8*96*256*256
#define S8_ELEMS  25165824  // 8*192*128*128
#define S16_ELEMS 12582912  // 8*384*64*64
#define OFF_S8   50331648
#define OFF_S16  75497472
#define OFF_S32  88080384

// GEMM tiling (bf16 m16n8k16, block 128x128, 8 warps of 64x32, 256 threads)
#define TBM 128
#define TBN 128
#define TBK 32              // k per smem stage (2 x k16 mma steps)
#define AS_W 20             // u32 words per A smem row (32 bf16 data + pad)
#define BS_W 136            // u32 words per B smem row (128 data + 8 pad)
#define A_STAGE_W (TBM * AS_W)        // 2560 words
#define B_STAGE_W ((TBK/2) * BS_W)    // 2176 words
#define SMEM_PLAIN_BYTES ((2*A_STAGE_W + 2*B_STAGE_W) * 4)          // 37888
#define SMEM_SPLIT_BYTES ((4*A_STAGE_W + 4*B_STAGE_W) * 4)          // 75776

#define MT (NTOK / TBM)     // 64 m-tiles
#define NT (C / TBN)        // 6  n-tiles
#define NB_COPY 148         // copy blocks PREPENDED per GEMM launch (proven R6/R8)
#define NB_CONV 256         // expert-weight convert blocks (gate launch only)

// ---------------------------------------------------------------------------
// Scratch (device globals: no allocation allowed)
// ---------------------------------------------------------------------------
__device__ __nv_bfloat16 g_Xb[NTOK * C];   // tokens hi bf16
__device__ __nv_bfloat16 g_Xl[NTOK * C];   // tokens lo bf16 (residual)
__device__ __nv_bfloat16 g_H [NTOK * C];   // expert hidden (compact, bf16)
__device__ float g_X [NTOK * C];           // Y (expert output, fp32, compact)
__device__ float g_G1[NTOK * C];           // gate hidden (fp32)
__device__ uint32_t g_gw1h[K2C * C];       // gate w1 hi, k-pair packed bf16x2
__device__ uint32_t g_gw1l[K2C * C];       // gate w1 lo (for fixup GEMM)
__device__ uint32_t g_ew1b[NE * K2C * C];  // expert w1 bf16 packed
__device__ uint32_t g_ew2b[NE * K2C * C];  // expert w2 bf16 packed
__device__ int   g_top[NTOK];
__device__ float g_gv[NTOK];
__device__ int   g_perm[NTOK];
__device__ int   g_tok2g[NTOK];
__device__ int   g_counts[NE];
__device__ int   g_offsets[NE + 1];
__device__ int   g_fill[NE];
__device__ int   g_nfix;
__device__ int   g_fix[NTOK];

// ---------------------------------------------------------------------------
// Helpers
// ---------------------------------------------------------------------------
__device__ __forceinline__ float gelu_tanh(float x) {
    float x3 = x * x * x;
    return 0.5f * x * (1.0f + tanhf(0.7978845608028654f * x + 0.035677408136300125f * x3));
}

__device__ __forceinline__ void cp_async16(uint32_t smem_dst, const void* gsrc, bool valid) {
    int sz = valid ? 16 : 0;
    asm volatile("cp.async.cg.shared.global [%0], [%1], 16, %2;\n"
                 :: "r"(smem_dst), "l"(gsrc), "r"(sz));
}
__device__ __forceinline__ void cp_commit() { asm volatile("cp.async.commit_group;\n"); }
__device__ __forceinline__ void cp_wait0()  { asm volatile("cp.async.wait_group 0;\n"); }

__device__ __forceinline__ void mma_bf16(float* c, const uint32_t* a, const uint32_t* b) {
    asm volatile(
        "mma.sync.aligned.m16n8k16.row.col.f32.bf16.bf16.f32 "
        "{%0,%1,%2,%3},{%4,%5,%6,%7},{%8,%9},{%0,%1,%2,%3};\n"
        : "+f"(c[0]), "+f"(c[1]), "+f"(c[2]), "+f"(c[3])
        : "r"(a[0]), "r"(a[1]), "r"(a[2]), "r"(a[3]), "r"(b[0]), "r"(b[1]));
}

// ldmatrix x4: A fragments for m16k16 (tiles in {m0-7/k0-7, m8-15/k0-7,
// m0-7/k8-15, m8-15/k8-15} order, matching mma a0..a3)
__device__ __forceinline__ void ldsm_x4(uint32_t* r, uint32_t addr) {
    asm volatile("ldmatrix.sync.aligned.m8n8.x4.shared.b16 {%0,%1,%2,%3}, [%4];"
                 : "=r"(r[0]), "=r"(r[1]), "=r"(r[2]), "=r"(r[3]) : "r"(addr));
}

__device__ __forceinline__ uint32_t pack_bf16x2(float v0, float v1) {
    uint32_t r;
    asm("cvt.rn.bf16x2.f32 %0, %1, %2;" : "=r"(r) : "f"(v1), "f"(v0));
    return r;
}

// grid-stride copy over 1024-float4 windows (cnt4 % 1024 == 0), stride NB_COPY
__device__ __forceinline__ void do_copy(int cblk, int tid,
                                        const float4* __restrict__ s,
                                        float4* __restrict__ d, int cnt4) {
    size_t i = (size_t)cblk * 1024 + tid;
    const size_t stride = (size_t)NB_COPY * 1024;
    for (; i < (size_t)cnt4; i += stride) {
        float4 v0 = s[i];
        float4 v1 = s[i + 256];
        float4 v2 = s[i + 512];
        float4 v3 = s[i + 768];
        d[i]       = v0;
        d[i + 256] = v1;
        d[i + 512] = v2;
        d[i + 768] = v3;
    }
}

// ---------------------------------------------------------------------------
// 1. prep: token transpose (hi/lo bf16) + gate-w1 split pack (hi + lo)
// ---------------------------------------------------------------------------
__global__ void prep_k(const float* __restrict__ s32, const float* __restrict__ gw1) {
    int blk = blockIdx.x;
    int tx = threadIdx.x, ty = threadIdx.y;   // (32, 8)

    if (blk < 6144) {
        __shared__ float tile[32][33];
        int bx = blk & 31;
        int t  = blk >> 5;
        int by = t % 24;
        int bz = t / 24;
        int c0 = by * 32, hw0 = bx * 32;
        if (blk == 0 && ty == 0 && tx < NE + 1) {
            if (tx < NE) g_counts[tx] = 0;
            else g_nfix = 0;
        }
        const float* src = s32 + ((size_t)bz * C + c0) * 1024 + hw0;
        #pragma unroll
        for (int j = 0; j < 32; j += 8)
            tile[ty + j][tx] = src[(ty + j) * 1024 + tx];
        __syncthreads();
        size_t dbase = ((size_t)(bz * 1024 + hw0)) * C + c0;
        #pragma unroll
        for (int j = 0; j < 32; j += 8) {
            float x = tile[tx][ty + j];
            __nv_bfloat16 h = __float2bfloat16(x);
            float r = x - __bfloat162float(h);
            size_t idx = dbase + (size_t)(ty + j) * C + tx;
            g_Xb[idx] = h;
            g_Xl[idx] = __float2bfloat16(r);
        }
    } else {
        // gate w1 split pack: [K2C][C] words, hi + lo
        int tid = ty * 32 + tx;
        const int total = K2C * C;
        for (int w = (blk - 6144) * 256 + tid; w < total; w += 256 * 256) {
            int k2 = w / C, n = w - k2 * C;
            float w0 = gw1[(size_t)(2 * k2) * C + n];
            float w1 = gw1[(size_t)(2 * k2 + 1) * C + n];
            float h0 = __bfloat162float(__float2bfloat16(w0));
            float h1 = __bfloat162float(__float2bfloat16(w1));
            g_gw1h[w] = pack_bf16x2(h0, h1);
            g_gw1l[w] = pack_bf16x2(w0 - h0, w1 - h1);
        }
    }
}

// ---------------------------------------------------------------------------
// bf16 GEMM: block 128x128, 8 warps (2m x 4n) of 64x32, 256 threads.
// A fragments via ldmatrix.x4 (one per m-tile per k-step).
//   MODE 0 (plain): G1 = gelu(Xb@gw1h+b1)  -> g_G1 (fp32); hosts copy+conv blocks
//   MODE 1 (plain): H  = gelu(gather(Xb)@ew1+b1) -> g_H (bf16)
//   MODE 2 (plain): Y  = (H@ew2+b2)*gate_val     -> g_X (fp32)
//   MODE 3 (split): exact hidden for fix-list tokens -> scatter to g_G1 rows
// ---------------------------------------------------------------------------
template <int MODE>
__launch_bounds__(256)
__global__ void mma_gemm_k(const float* __restrict__ Ball,
                           const float4* __restrict__ csrc, float4* __restrict__ cdst, int cnt4,
                           const float* __restrict__ cvt1, const float* __restrict__ cvt2,
                           int nbPre) {
    constexpr bool SPLIT = (MODE == 3);
    const int blk = blockIdx.x;
    const int tid = threadIdx.x;

    if (MODE != 3 && blk < NB_COPY) { do_copy(blk, tid, csrc, cdst, cnt4); return; }

    if (MODE == 0 && blk < nbPre) {
        const int cb = blk - NB_COPY;
        const int WCNT = NE * K2C * C;
        for (int w = cb * 256 + tid; w < 2 * WCNT; w += NB_CONV * 256) {
            int wi = w;
            const float* src; uint32_t* dst;
            if (wi < WCNT) { src = cvt1; dst = g_ew1b; }
            else           { wi -= WCNT; src = cvt2; dst = g_ew2b; }
            int k2g = wi / C, n = wi - k2g * C;
            float w0 = src[(size_t)(2 * k2g) * C + n];
            float w1 = src[(size_t)(2 * k2g + 1) * C + n];
            dst[wi] = pack_bf16x2(w0, w1);
        }
        return;
    }

    // ---- GEMM tile mapping ----------------------------------------------
    const int gblk = blk - ((MODE == 3) ? 0 : nbPre);
    int e, bx, by;
    if (MODE == 0 || MODE == 3) { e = 0; bx = gblk & (MT - 1); by = gblk >> 6; }
    else { e = gblk / (MT * NT); int r = gblk - e * (MT * NT); bx = r & (MT - 1); by = r >> 6; }

    int base, cnt;
    if      (MODE == 0) { base = 0; cnt = NTOK; }
    else if (MODE == 3) { base = 0; cnt = g_nfix; }
    else                { base = g_offsets[e]; cnt = g_offsets[e + 1] - base; }

    const int m0 = bx * TBM;
    if (m0 >= cnt) return;
    const int n0 = by * TBN;

    const uint32_t* Wh = (MODE == 0 || MODE == 3) ? g_gw1h
                        : (MODE == 1) ? (g_ew1b + (size_t)e * K2C * C)
                                      : (g_ew2b + (size_t)e * K2C * C);
    const uint32_t* Wl = g_gw1l;   // only used when SPLIT
    const float* bias  = Ball + ((MODE == 1 || MODE == 2) ? e * C : 0);

    extern __shared__ uint32_t sm[];
    uint32_t* AhB = sm;
    uint32_t* AlB = sm + 2 * A_STAGE_W;
    uint32_t* BhB = sm + (SPLIT ? 4 : 2) * A_STAGE_W;
    uint32_t* BlB = BhB + 2 * B_STAGE_W;
    const uint32_t sAh = (uint32_t)__cvta_generic_to_shared(AhB);
    const uint32_t sAl = (uint32_t)__cvta_generic_to_shared(AlB);
    const uint32_t sBh = (uint32_t)__cvta_generic_to_shared(BhB);
    const uint32_t sBl = (uint32_t)__cvta_generic_to_shared(BlB);

    const int wid  = tid >> 5;
    const int lane = tid & 31;
    const int g    = lane >> 2;
    const int tig  = lane & 3;
    const int mW   = (wid & 1) * 64;     // m 0-63 or 64-127
    const int nW   = (wid >> 1) * 32;    // n slice of 32 per warp pair-group

    // ldmatrix per-lane byte offsets (relative to stage base), one per m-tile.
    // lane 0-7: rows m0-7 @word 0 | 8-15: m8-15 @0 | 16-23: m0-7 @+4 | 24-31: m8-15 @+4
    uint32_t aoff[4];
    {
        const int lrow = lane & 15;
        const int lsel = lane >> 4;
        #pragma unroll
        for (int mt = 0; mt < 4; mt++)
            aoff[mt] = (uint32_t)(((mW + mt * 16 + lrow) * AS_W + lsel * 4) * 4);
    }

    // A loader: 2 x 16B chunks / thread / stage (per array)
    const __nv_bfloat16* Asrc = (MODE == 2) ? g_H : g_Xb;
    const uint8_t* srcA[2]; const uint8_t* srcAL[2]; uint32_t dstA[2]; bool vA[2];
    #pragma unroll
    for (int i = 0; i < 2; i++) {
        int q = tid + i * 256;
        int chunk = q >> 7;          // 0..3
        int row   = q & 127;
        int m = m0 + row;
        bool v = (m < cnt);
        int ar = 0;
        if (v) {
            if      (MODE == 1) ar = g_perm[base + m];
            else if (MODE == 2) ar = base + m;
            else if (MODE == 3) ar = g_fix[m];
            else                ar = m;
        }
        size_t boff = (size_t)ar * C * 2 + chunk * 16;
        srcA[i]  = (const uint8_t*)Asrc + boff;
        srcAL[i] = (const uint8_t*)g_Xl + boff;
        dstA[i]  = (uint32_t)(row * AS_W + chunk * 4) * 4u;
        vA[i] = v;
    }
    // B loader: 2 x 16B chunks / thread / stage
    size_t srcBoff[2]; uint32_t dstB[2];
    #pragma unroll
    for (int i = 0; i < 2; i++) {
        int q = tid + i * 256;
        int k2r = q >> 5;            // 0..15
        int c   = q & 31;            // 0..31
        srcBoff[i] = (size_t)k2r * C + n0 + c * 4;
        dstB[i]    = (uint32_t)(k2r * BS_W + c * 4) * 4u;
    }

    float acc[4][4][4];
    #pragma unroll
    for (int mt = 0; mt < 4; mt++)
        #pragma unroll
        for (int nt = 0; nt < 4; nt++)
            #pragma unroll
            for (int r = 0; r < 4; r++) acc[mt][nt][r] = 0.f;

    const int T = C / TBK;  // 24

    // prologue: stage 0
    #pragma unroll
    for (int i = 0; i < 2; i++) cp_async16(sAh + dstA[i], srcA[i], vA[i]);
    if (SPLIT)
        #pragma unroll
        for (int i = 0; i < 2; i++) cp_async16(sAl + dstA[i], srcAL[i], vA[i]);
    #pragma unroll
    for (int i = 0; i < 2; i++) cp_async16(sBh + dstB[i], Wh + srcBoff[i], true);
    if (SPLIT)
        #pragma unroll
        for (int i = 0; i < 2; i++) cp_async16(sBl + dstB[i], Wl + srcBoff[i], true);
    cp_commit();

    for (int t = 0; t < T; t++) {
        const int cur = t & 1;
        cp_wait0();
        __syncthreads();

        if (t + 1 < T) {
            const int nxt = cur ^ 1;
            const int kb = (t + 1) * (TBK * 2);                 // bytes into A rows
            const size_t kw = (size_t)(t + 1) * (TBK / 2) * C;  // words into W
            #pragma unroll
            for (int i = 0; i < 2; i++)
                cp_async16(sAh + nxt * (A_STAGE_W * 4) + dstA[i], srcA[i] + kb, vA[i]);
            if (SPLIT)
                #pragma unroll
                for (int i = 0; i < 2; i++)
                    cp_async16(sAl + nxt * (A_STAGE_W * 4) + dstA[i], srcAL[i] + kb, vA[i]);
            #pragma unroll
            for (int i = 0; i < 2; i++)
                cp_async16(sBh + nxt * (B_STAGE_W * 4) + dstB[i], Wh + srcBoff[i] + kw, true);
            if (SPLIT)
                #pragma unroll
                for (int i = 0; i < 2; i++)
                    cp_async16(sBl + nxt * (B_STAGE_W * 4) + dstB[i], Wl + srcBoff[i] + kw, true);
            cp_commit();
        }

        const uint32_t aBase  = sAh + cur * (A_STAGE_W * 4);
        const uint32_t alBase = sAl + cur * (A_STAGE_W * 4);
        const uint32_t* Bhc = BhB + cur * B_STAGE_W;
        const uint32_t* Blc = BlB + cur * B_STAGE_W;

        #pragma unroll
        for (int ks = 0; ks < 2; ks++) {
            const int k8 = ks * 8;
            const uint32_t kbyte = (uint32_t)(k8 * 4);
            uint32_t bh[4][2], bl[4][2];
            #pragma unroll
            for (int nt = 0; nt < 4; nt++) {
                const int n = nW + nt * 8 + g;
                bh[nt][0] = Bhc[(k8 + tig)     * BS_W + n];
                bh[nt][1] = Bhc[(k8 + tig + 4) * BS_W + n];
                if (SPLIT) {
                    bl[nt][0] = Blc[(k8 + tig)     * BS_W + n];
                    bl[nt][1] = Blc[(k8 + tig + 4) * BS_W + n];
                }
            }
            #pragma unroll
            for (int mt = 0; mt < 4; mt++) {
                uint32_t ah[4], al[4];
                ldsm_x4(ah, aBase + aoff[mt] + kbyte);
                if (SPLIT) ldsm_x4(al, alBase + aoff[mt] + kbyte);
                #pragma unroll
                for (int nt = 0; nt < 4; nt++) {
                    mma_bf16(acc[mt][nt], ah, bh[nt]);
                    if (SPLIT) {
                        mma_bf16(acc[mt][nt], al, bh[nt]);
                        mma_bf16(acc[mt][nt], ah, bl[nt]);
                    }
                }
            }
        }
        __syncthreads();
    }

    // ---- epilogue --------------------------------------------------------
    #pragma unroll
    for (int mt = 0; mt < 4; mt++) {
        #pragma unroll
        for (int half = 0; half < 2; half++) {
            const int m = m0 + mW + mt * 16 + g + half * 8;
            if (m >= cnt) continue;
            float gv = 1.f;
            if (MODE == 2) gv = g_gv[g_perm[base + m]];
            int drow = 0;
            if      (MODE == 0) drow = m;
            else if (MODE == 3) drow = g_fix[m];
            #pragma unroll
            for (int nt = 0; nt < 4; nt++) {
                const int col = n0 + nW + nt * 8 + tig * 2;
                float2 bv = *(const float2*)(bias + col);
                float v0 = acc[mt][nt][half * 2 + 0] + bv.x;
                float v1 = acc[mt][nt][half * 2 + 1] + bv.y;
                if (MODE == 0 || MODE == 3) {
                    float* orow = g_G1 + (size_t)drow * C;
                    *(float2*)(orow + col) = make_float2(gelu_tanh(v0), gelu_tanh(v1));
                } else if (MODE == 1) {
                    __nv_bfloat162* hrow = (__nv_bfloat162*)(g_H + (size_t)(base + m) * C);
                    hrow[col >> 1] = __floats2bfloat162_rn(gelu_tanh(v0), gelu_tanh(v1));
                } else {
                    float* orow = g_X + (size_t)(base + m) * C;
                    *(float2*)(orow + col) = make_float2(v0 * gv, v1 * gv);
                }
            }
        }
    }
}

// ---------------------------------------------------------------------------
// 3. logits from G1 (bf16-noised). Confident tokens finalize; near-ties go to
//    the fix list for exact recompute via the MODE-3 GEMM.
// ---------------------------------------------------------------------------
__global__ void gate_k(const float* __restrict__ w2, const float* __restrict__ b2) {
    int warp = (blockIdx.x * blockDim.x + threadIdx.x) >> 5;
    int lane = threadIdx.x & 31;
    if (warp >= NTOK) return;
    const float* g = g_G1 + (size_t)warp * C;
    float l0 = 0.f, l1 = 0.f, l2 = 0.f, l3 = 0.f;
    for (int c = lane; c < C; c += 32) {
        float x = g[c];
        float4 wv = *(const float4*)(w2 + c * 4);
        l0 = fmaf(x, wv.x, l0);
        l1 = fmaf(x, wv.y, l1);
        l2 = fmaf(x, wv.z, l2);
        l3 = fmaf(x, wv.w, l3);
    }
    #pragma unroll
    for (int o = 16; o; o >>= 1) {
        l0 += __shfl_xor_sync(0xffffffffu, l0, o);
        l1 += __shfl_xor_sync(0xffffffffu, l1, o);
        l2 += __shfl_xor_sync(0xffffffffu, l2, o);
        l3 += __shfl_xor_sync(0xffffffffu, l3, o);
    }
    if (lane == 0) {
        l0 += b2[0]; l1 += b2[1]; l2 += b2[2]; l3 += b2[3];
        float m = l0; int idx = 0;
        if (l1 > m) { m = l1; idx = 1; }   // strict '>' keeps first max (jnp.argmax)
        if (l2 > m) { m = l2; idx = 2; }
        if (l3 > m) { m = l3; idx = 3; }
        float m2 = -3.0e38f;
        if (idx != 0 && l0 > m2) m2 = l0;
        if (idx != 1 && l1 > m2) m2 = l1;
        if (idx != 2 && l2 > m2) m2 = l2;
        if (idx != 3 && l3 > m2) m2 = l3;
        float thresh = 0.004f + 0.003f * fabsf(m);   // ~5 sigma of bf16 gap noise
        if (m - m2 > thresh) {
            float s = expf(l0 - m) + expf(l1 - m) + expf(l2 - m) + expf(l3 - m);
            g_top[warp] = idx;
            g_gv[warp]  = 1.0f / s;
            atomicAdd(&g_counts[idx], 1);
        } else {
            int p = atomicAdd(&g_nfix, 1);
            g_fix[p] = warp;
        }
    }
}

// ---------------------------------------------------------------------------
// 3b. finalize routing for fix-list tokens from their refreshed (exact) G1 rows
// ---------------------------------------------------------------------------
__global__ void fix_gate_k(const float* __restrict__ w2, const float* __restrict__ b2) {
    int i = (blockIdx.x * blockDim.x + threadIdx.x) >> 5;
    int lane = threadIdx.x & 31;
    if (i >= g_nfix) return;
    int n = g_fix[i];
    const float* g = g_G1 + (size_t)n * C;
    float l0 = 0.f, l1 = 0.f, l2 = 0.f, l3 = 0.f;
    for (int c = lane; c < C; c += 32) {
        float x = g[c];
        float4 wv = *(const float4*)(w2 + c * 4);
        l0 = fmaf(x, wv.x, l0);
        l1 = fmaf(x, wv.y, l1);
        l2 = fmaf(x, wv.z, l2);
        l3 = fmaf(x, wv.w, l3);
    }
    #pragma unroll
    for (int o = 16; o; o >>= 1) {
        l0 += __shfl_xor_sync(0xffffffffu, l0, o);
        l1 += __shfl_xor_sync(0xffffffffu, l1, o);
        l2 += __shfl_xor_sync(0xffffffffu, l2, o);
        l3 += __shfl_xor_sync(0xffffffffu, l3, o);
    }
    if (lane == 0) {
        l0 += b2[0]; l1 += b2[1]; l2 += b2[2]; l3 += b2[3];
        float m = l0; int idx = 0;
        if (l1 > m) { m = l1; idx = 1; }
        if (l2 > m) { m = l2; idx = 2; }
        if (l3 > m) { m = l3; idx = 3; }
        float s = expf(l0 - m) + expf(l1 - m) + expf(l2 - m) + expf(l3 - m);
        g_top[n] = idx;
        g_gv[n]  = 1.0f / s;
        atomicAdd(&g_counts[idx], 1);
    }
}

// ---------------------------------------------------------------------------
// 4. tiny exclusive scan + reset fill cursors
// ---------------------------------------------------------------------------
__global__ void scan_k() {
    if (threadIdx.x == 0) {
        int s = 0;
        #pragma unroll
        for (int e = 0; e < NE; e++) {
            g_offsets[e] = s;
            s += g_counts[e];
            g_fill[e] = 0;
        }
        g_offsets[NE] = s;
    }
}

// ---------------------------------------------------------------------------
// 5. build permutation (token -> compact position, grouped by expert)
// ---------------------------------------------------------------------------
__global__ void perm_k() {
    int n = blockIdx.x * blockDim.x + threadIdx.x;
    if (n >= NTOK) return;
    int e = g_top[n];
    int pos = atomicAdd(&g_fill[e], 1);
    int gg = g_offsets[e] + pos;
    g_perm[gg]  = n;
    g_tok2g[n]  = gg;
}

// ---------------------------------------------------------------------------
// 8. coalesced scatter back to BCHW + residual
// ---------------------------------------------------------------------------
__global__ void scatter_k(const float* __restrict__ s32, float* __restrict__ out32) {
    __shared__ float tile[32][33];
    int b = blockIdx.z, c0 = blockIdx.y * 32, hw0 = blockIdx.x * 32;
    int tx = threadIdx.x, ty = threadIdx.y;   // (32, 8)
    for (int t = ty; t < 32; t += 8) {
        int n = b * 1024 + hw0 + t;
        int gg = g_tok2g[n];
        tile[t][tx] = g_X[(size_t)gg * C + c0 + tx];
    }
    __syncthreads();
    int ibase = b * (C * 1024) + hw0;
    #pragma unroll
    for (int j = 0; j < 4; j++) {
        int c = c0 + ty + 8 * j;
        int idx = ibase + c * 1024 + tx;
        out32[idx] = tile[tx][ty + 8 * j] + s32[idx];
    }
}

// ---------------------------------------------------------------------------
// launch
// ---------------------------------------------------------------------------
extern "C" void kernel_launch(void* const* d_in, const int* in_sizes, int n_in,
                              void* d_out, int out_size) {
    const float* s4  = (const float*)d_in[0];
    const float* s8  = (const float*)d_in[1];
    const float* s16 = (const float*)d_in[2];
    const float* s32 = (const float*)d_in[3];
    const float* gw1 = (const float*)d_in[4];
    const float* gb1 = (const float*)d_in[5];
    const float* gw2 = (const float*)d_in[6];
    const float* gb2 = (const float*)d_in[7];
    const float* ew1 = (const float*)d_in[8];
    const float* eb1 = (const float*)d_in[9];
    const float* ew2 = (const float*)d_in[10];
    const float* eb2 = (const float*)d_in[11];
    float* out = (float*)d_out;

    cudaFuncSetAttribute(mma_gemm_k<3>, cudaFuncAttributeMaxDynamicSharedMemorySize, SMEM_SPLIT_BYTES);

    // prep: token transpose (hi/lo bf16) + gate w1 split pack
    prep_k<<<6144 + 256, dim3(32, 8)>>>(s32, gw1);

    // gate hidden (plain bf16) + s4 copy + expert weight pack, one launch (R6 layout)
    mma_gemm_k<0><<<NB_COPY + NB_CONV + MT * NT, 256, SMEM_PLAIN_BYTES>>>(
        gb1, (const float4*)s4, (float4*)out, S4_ELEMS / 4, ew1, ew2, NB_COPY + NB_CONV);

    // routing: confident tokens finalize; near-ties get exact split-bf16 recompute
    gate_k<<<(NTOK * 32) / 256, 256>>>(gw2, gb2);
    mma_gemm_k<3><<<MT * NT, 256, SMEM_SPLIT_BYTES>>>(
        gb1, nullptr, nullptr, 0, nullptr, nullptr, 0);
    fix_gate_k<<<(NTOK * 32) / 256, 256>>>(gw2, gb2);
    scan_k<<<1, 1>>>();
    perm_k<<<NTOK / 256, 256>>>();

    // expert up (bf16) + s8 copy
    mma_gemm_k<1><<<NB_COPY + MT * NT * NE, 256, SMEM_PLAIN_BYTES>>>(
        eb1, (const float4*)s8, (float4*)(out + OFF_S8), S8_ELEMS / 4,
        nullptr, nullptr, NB_COPY);

    // expert down (bf16) + s16 copy
    mma_gemm_k<2><<<NB_COPY + MT * NT * NE, 256, SMEM_PLAIN_BYTES>>>(
        eb2, (const float4*)s16, (float4*)(out + OFF_S16), S16_ELEMS / 4,
        nullptr, nullptr, NB_COPY);

    // scatter + residual into out32
    scatter_k<<<dim3(32, 24, 8), dim3(32, 8)>>>(s32, out + OFF_S32);
}